// round 13
// baseline (speedup 1.0000x reference)
#include <cuda_runtime.h>
#include <cstddef>

#define NSPEC 10
#define KCH   64
#define D     9
#define NA1   3
#define NA2   8
#define NA3   18
#define ATOT  29
#define NEK   (NSPEC * KCH)   // 640 (species, channel) combos
#define NM    220             // C(12,3): monomials i<=j<=l over 10 vars (v9 == 1)
#define ROWF  12              // padded floats per monomial row in g_S
#define PROW  20              // floats per PAIR row in smem (9 outputs x 2 + 2 pad)
#define RROW  13              // reduction/x row stride (odd -> conflict-free banks)
#define ABLK  64              // atoms per eval block
#define Q1    56              // even quarter boundaries (pairs never straddle)
#define Q2    112
#define Q3    168

// Scratch (device global — allocation-free per harness rules)
__device__ float g_S[(size_t)NEK * NM * ROWF];    // S[ek][m][o] symmetrized coeffs

// ---------------------------------------------------------------------------
// packed f32x2 helpers (sm_103a FFMA2 — PTX only)
// ---------------------------------------------------------------------------
__device__ __forceinline__ void ffma2(unsigned long long& d,
                                      unsigned long long a,
                                      unsigned long long b) {
    asm("fma.rn.f32x2 %0, %1, %2, %0;" : "+l"(d) : "l"(a), "l"(b));
}
__device__ __forceinline__ unsigned long long dup_f32(float t) {
    unsigned long long r;
    asm("mov.b64 %0, {%1, %1};" : "=l"(r) : "r"(__float_as_uint(t)));
    return r;
}
__device__ __forceinline__ unsigned long long pack_f32x2(float lo, float hi) {
    unsigned long long r;
    asm("mov.b64 %0, {%1, %2};" : "=l"(r)
        : "r"(__float_as_uint(lo)), "r"(__float_as_uint(hi)));
    return r;
}
__device__ __forceinline__ void unpack2(unsigned long long p, float& lo, float& hi) {
    unsigned a, b;
    asm("mov.b64 {%0, %1}, %2;" : "=r"(a), "=r"(b) : "l"(p));
    lo = __uint_as_float(a); hi = __uint_as_float(b);
}

// ---------------------------------------------------------------------------
// Kernel B: symmetrized coefficients (UNCHANGED from passing round 10).
// One block per monomial m (220 blocks), 640 threads = (e,k).
// ---------------------------------------------------------------------------
__global__ void __launch_bounds__(NEK)
coeff_kernel(const float* __restrict__ w,
             const float* __restrict__ proj,
             const float* __restrict__ U1,
             const float* __restrict__ U2,
             const float* __restrict__ U3) {
    const int m = blockIdx.x;
    const int t = threadIdx.x;

    // prefetch w for phase 3 (hides LDG latency under phases 1-2)
    const int e = t >> 6, k = t & 63;
    float wr[ATOT];
#pragma unroll
    for (int a = 0; a < ATOT; a++)
        wr[a] = w[((size_t)e * ATOT + a) * KCH + k];

    // closed-form decode m -> (mi <= mj <= ml) over 10 vars
    int rem = m, mi = 0, mj, ml;
#pragma unroll
    for (int i = 0; i < 10; i++) {
        int tt = 10 - i, c = tt * (tt + 1) / 2;
        if (rem >= c) rem -= c; else { mi = i; break; }
    }
    mj = mi;
#pragma unroll
    for (int j = 0; j < 10; j++) {
        if (j < mi) continue;
        int c = 10 - j;
        if (rem >= c) rem -= c; else { mj = j; break; }
    }
    ml = mj + rem;

    const int deg  = (ml < 9) ? 3 : (mj < 9) ? 2 : (mi < 9) ? 1 : 0;
    const int aoff = (deg == 3) ? (NA1 + NA2) : (deg == 2) ? NA1 : 0;

    __shared__ __align__(16) float UsT[NA3 * 12];   // [b][o], padded
    __shared__ __align__(16) float V[ATOT * 12];    // [a][o], padded

    if (t < NA3 * 12) UsT[t] = 0.f;
    __syncthreads();

    if (t < 9 * NA3) {
        int o = t / NA3, a = t % NA3;
        float s = 0.f;
        if (deg == 3) {
            const size_t ob = (size_t)o * 9;
            float s6 =
                U3[(((ob + mi) * 9 + mj) * 9 + ml) * NA3 + a] +
                U3[(((ob + mi) * 9 + ml) * 9 + mj) * NA3 + a] +
                U3[(((ob + mj) * 9 + mi) * 9 + ml) * NA3 + a] +
                U3[(((ob + mj) * 9 + ml) * 9 + mi) * NA3 + a] +
                U3[(((ob + ml) * 9 + mi) * 9 + mj) * NA3 + a] +
                U3[(((ob + ml) * 9 + mj) * 9 + mi) * NA3 + a];
            float scale = (mi == ml) ? (1.f / 6.f)
                         : ((mi == mj || mj == ml) ? 0.5f : 1.f);
            s = s6 * scale;
        } else if (deg == 2 && a < NA2) {
            float s2 = U2[(((size_t)o * 9 + mi) * 9 + mj) * NA2 + a] +
                       U2[(((size_t)o * 9 + mj) * 9 + mi) * NA2 + a];
            s = (mi == mj) ? 0.5f * s2 : s2;
        } else if (deg == 1 && a < NA1) {
            s = U1[((size_t)o * 9 + mi) * NA1 + a];
        }
        UsT[a * 12 + o] = s;
    }
    __syncthreads();

    // Phase 2: V[a][o]  (compile-time unrolled per degree)
    if (t < ATOT * 12) {
        int a = t / 12, o = t % 12;
        float s = 0.f;
        if (o < 9) {
            if (deg == 3) {
#pragma unroll
                for (int b = 0; b < NA3; b++)
                    s = fmaf(proj[a * ATOT + aoff + b], UsT[b * 12 + o], s);
            } else if (deg == 2) {
#pragma unroll
                for (int b = 0; b < NA2; b++)
                    s = fmaf(proj[a * ATOT + aoff + b], UsT[b * 12 + o], s);
            } else if (deg == 1) {
#pragma unroll
                for (int b = 0; b < NA1; b++)
                    s = fmaf(proj[a * ATOT + aoff + b], UsT[b * 12 + o], s);
            }
        }
        V[a * 12 + o] = s;
    }
    __syncthreads();

    // Phase 3: per (e,k) thread, w already in registers
    unsigned long long a01 = 0, a23 = 0, a45 = 0, a67 = 0;
    float a8 = 0.f;
#pragma unroll
    for (int a = 0; a < ATOT; a++) {
        const float* row = V + a * 12;
        ulonglong2 cA = *(const ulonglong2*)row;
        ulonglong2 cB = *(const ulonglong2*)(row + 4);
        float c8 = row[8];
        unsigned long long wv = dup_f32(wr[a]);
        ffma2(a01, cA.x, wv);
        ffma2(a23, cA.y, wv);
        ffma2(a45, cB.x, wv);
        ffma2(a67, cB.y, wv);
        a8 = fmaf(c8, wr[a], a8);
    }

    float c9[9];
    unpack2(a01, c9[0], c9[1]);
    unpack2(a23, c9[2], c9[3]);
    unpack2(a45, c9[4], c9[5]);
    unpack2(a67, c9[6], c9[7]);
    c9[8] = a8;

    float* dst = g_S + ((size_t)t * NM + m) * ROWF;
    ((float4*)dst)[0] = make_float4(c9[0], c9[1], c9[2], c9[3]);
    ((float4*)dst)[1] = make_float4(c9[4], c9[5], c9[6], c9[7]);
    ((float4*)dst)[2] = make_float4(c9[8], 0.f, 0.f, 0.f);
}

// ---------------------------------------------------------------------------
// Eval inner body (PAIR version): accumulate monomial pairs in [MS, ME).
// Smem layout: pair p row of PROW floats: [c(2p,o)|c(2p+1,o)] for o=0..8.
// One ffma2 per output accumulates BOTH monomials (lo/hi halves).
// ---------------------------------------------------------------------------
template <int MS, int ME>
__device__ __forceinline__ void eval_pairs(const float* __restrict__ Cs,
                                           const float v[10], float r[9]) {
    unsigned long long ac0 = 0, ac1 = 0, ac2 = 0, ac3 = 0, ac4 = 0,
                       ac5 = 0, ac6 = 0, ac7 = 0, ac8 = 0;
    float tm0 = 0.f;
    int m = 0;
#pragma unroll
    for (int i = 0; i < 10; i++) {
#pragma unroll
        for (int j = i; j < 10; j++) {
            float pij = v[i] * v[j];
#pragma unroll
            for (int l = j; l < 10; l++) {
                if (m >= MS && m < ME) {
                    float tm = pij * v[l];
                    if ((m & 1) == 0) {
                        tm0 = tm;                       // stash even monomial
                    } else {
                        unsigned long long tp = pack_f32x2(tm0, tm);
                        const float* row = Cs + (m >> 1) * PROW;
                        ulonglong2 cA = *(const ulonglong2*)row;        // o0,o1
                        ulonglong2 cB = *(const ulonglong2*)(row + 4);  // o2,o3
                        ulonglong2 cC = *(const ulonglong2*)(row + 8);  // o4,o5
                        ulonglong2 cD = *(const ulonglong2*)(row + 12); // o6,o7
                        unsigned long long c8 = *(const unsigned long long*)(row + 16);
                        ffma2(ac0, cA.x, tp);
                        ffma2(ac1, cA.y, tp);
                        ffma2(ac2, cB.x, tp);
                        ffma2(ac3, cB.y, tp);
                        ffma2(ac4, cC.x, tp);
                        ffma2(ac5, cC.y, tp);
                        ffma2(ac6, cD.x, tp);
                        ffma2(ac7, cD.y, tp);
                        ffma2(ac8, c8,   tp);
                    }
                }
                m++;
            }
        }
    }
    float lo, hi;
    unpack2(ac0, lo, hi); r[0] = lo + hi;
    unpack2(ac1, lo, hi); r[1] = lo + hi;
    unpack2(ac2, lo, hi); r[2] = lo + hi;
    unpack2(ac3, lo, hi); r[3] = lo + hi;
    unpack2(ac4, lo, hi); r[4] = lo + hi;
    unpack2(ac5, lo, hi); r[5] = lo + hi;
    unpack2(ac6, lo, hi); r[6] = lo + hi;
    unpack2(ac7, lo, hi); r[7] = lo + hi;
    unpack2(ac8, lo, hi); r[8] = lo + hi;
}

// ---------------------------------------------------------------------------
// Kernel C: evaluate. 256 threads; block = (k, e, half): 64 atoms x 4 quarters.
// Cs staged into smem in PAIR-interleaved layout (transpose done here so the
// coeff kernel stays unchanged). x / out staged coalesced as before.
// ---------------------------------------------------------------------------
__global__ void __launch_bounds__(256, 5)
eval_kernel(const float* __restrict__ x,
            const int* __restrict__ counts,
            float* __restrict__ out) {
    const int k = blockIdx.x;
    const int e = blockIdx.y;
    const int h = blockIdx.z;               // atom half: 0 or 1
    const int ek = e * KCH + k;
    const int abase = h * ABLK;

    __shared__ __align__(16) float Cs[(NM / 2) * PROW];   // 2200 floats
    __shared__ float Red[3 * ABLK * RROW];
    __shared__ float Xs[ABLK * RROW];

    // Stage + pair-transpose coefficients: g_S[m][o] -> Cs[(m/2)*20 + o*2 + (m&1)]
    {
        const float* src = g_S + (size_t)ek * NM * ROWF;
        for (int idx = threadIdx.x; idx < NM * ROWF; idx += blockDim.x) {
            int m = idx / ROWF, o = idx - m * ROWF;
            float val = src[idx];
            if (o < 9)
                Cs[(m >> 1) * PROW + o * 2 + (m & 1)] = val;
        }
    }

    int start = 0, cnt = 0;
#pragma unroll
    for (int t = 0; t < NSPEC; t++) {
        int c = counts[t];
        if (t < e) start += c;
        if (t == e) cnt = c;
    }
    const int lcnt = min(ABLK, cnt - abase);  // valid local atoms (>= 38 always)

    // Coalesced cooperative x stage
    for (int idx = threadIdx.x; idx < ABLK * D; idx += blockDim.x) {
        int atom = idx / D, d = idx - atom * D;
        int a = (atom < lcnt) ? atom : (lcnt - 1);     // clamp
        int n = start + abase + a;
        Xs[atom * RROW + d] = x[((size_t)n * KCH + k) * D + d];
    }
    __syncthreads();

    const int tid  = threadIdx.x;
    const int atom = tid & (ABLK - 1);
    const int q    = tid >> 6;

    float v[10];
#pragma unroll
    for (int t = 0; t < 9; t++) v[t] = Xs[atom * RROW + t];
    v[9] = 1.f;

    float r[9];
    if (q == 0)      eval_pairs<0,  Q1>(Cs, v, r);
    else if (q == 1) eval_pairs<Q1, Q2>(Cs, v, r);
    else if (q == 2) eval_pairs<Q2, Q3>(Cs, v, r);
    else             eval_pairs<Q3, NM>(Cs, v, r);

    if (q != 0) {
        float* rr = Red + ((q - 1) * ABLK + atom) * RROW;
#pragma unroll
        for (int o = 0; o < 9; o++) rr[o] = r[o];
    }
    __syncthreads();

    // q0 reduces into Xs (x no longer needed), then coalesced store sweep
    if (q == 0) {
        const float* r1 = Red + (0 * ABLK + atom) * RROW;
        const float* r2 = Red + (1 * ABLK + atom) * RROW;
        const float* r3 = Red + (2 * ABLK + atom) * RROW;
        float* rr = Xs + atom * RROW;
#pragma unroll
        for (int o = 0; o < 9; o++)
            rr[o] = (r[o] + r1[o]) + (r2[o] + r3[o]);
    }
    __syncthreads();

    for (int idx = threadIdx.x; idx < lcnt * D; idx += blockDim.x) {
        int atom2 = idx / D, d = idx - atom2 * D;
        int n = start + abase + atom2;
        out[((size_t)n * KCH + k) * D + d] = Xs[atom2 * RROW + d];
    }
}

// ---------------------------------------------------------------------------
extern "C" void kernel_launch(void* const* d_in, const int* in_sizes, int n_in,
                              void* d_out, int out_size) {
    const float* x      = (const float*)d_in[0];
    const int*   counts = (const int*)  d_in[1];
    const float* w      = (const float*)d_in[2];
    const float* proj   = (const float*)d_in[3];
    const float* U1     = (const float*)d_in[4];
    const float* U2     = (const float*)d_in[5];
    const float* U3     = (const float*)d_in[6];
    float* out = (float*)d_out;

    coeff_kernel<<<NM, NEK>>>(w, proj, U1, U2, U3);
    dim3 grid(KCH, NSPEC, 2);
    eval_kernel<<<grid, 256>>>(x, counts, out);
}

// round 15
// speedup vs baseline: 1.1293x; 1.1293x over previous
#include <cuda_runtime.h>
#include <cstddef>

#define NSPEC 10
#define KCH   64
#define D     9
#define NA1   3
#define NA2   8
#define NA3   18
#define ATOT  29
#define NEK   (NSPEC * KCH)   // 640 (species, channel) combos
#define NM    220             // C(12,3): monomials i<=j<=l over 10 vars (v9 == 1)
#define NPAIR (NM / 2)        // 110 monomial pairs
#define PROW  20              // floats per pair row: [o0e,o0o,...,o8e,o8o,pad,pad]
#define PBLK  (NPAIR * PROW)  // 2200 floats per (e,k)
#define VROW  20              // V pair row stride in coeff smem
#define RROW  13              // reduction/x row stride (odd -> conflict-free)
#define T1    74              // third boundaries in monomial units (even!)
#define T2    148

// Scratch (device global — allocation-free per harness rules)
__device__ float g_SP[(size_t)NEK * PBLK];   // pair-interleaved coeffs, 5.6 MB

// ---------------------------------------------------------------------------
// packed f32x2 helpers (sm_103a FFMA2 — PTX only)
// ---------------------------------------------------------------------------
__device__ __forceinline__ void ffma2(unsigned long long& d,
                                      unsigned long long a,
                                      unsigned long long b) {
    asm("fma.rn.f32x2 %0, %1, %2, %0;" : "+l"(d) : "l"(a), "l"(b));
}
__device__ __forceinline__ unsigned long long dup_f32(float t) {
    unsigned long long r;
    asm("mov.b64 %0, {%1, %1};" : "=l"(r) : "r"(__float_as_uint(t)));
    return r;
}
__device__ __forceinline__ unsigned long long pack_f32x2(float lo, float hi) {
    unsigned long long r;
    asm("mov.b64 %0, {%1, %2};" : "=l"(r)
        : "r"(__float_as_uint(lo)), "r"(__float_as_uint(hi)));
    return r;
}
__device__ __forceinline__ void unpack2(unsigned long long p, float& lo, float& hi) {
    unsigned a, b;
    asm("mov.b64 {%0, %1}, %2;" : "=r"(a), "=r"(b) : "l"(p));
    lo = __uint_as_float(a); hi = __uint_as_float(b);
}

// ---------------------------------------------------------------------------
// Monomial decode + symmetrized-U helpers for the coeff kernel
// ---------------------------------------------------------------------------
__device__ __forceinline__ void decode_m(int m, int& mi, int& mj, int& ml) {
    int rem = m; mi = 0;
#pragma unroll
    for (int i = 0; i < 10; i++) {
        int tt = 10 - i, c = tt * (tt + 1) / 2;
        if (rem >= c) rem -= c; else { mi = i; break; }
    }
    mj = mi;
#pragma unroll
    for (int j = 0; j < 10; j++) {
        if (j < mi) continue;
        int c = 10 - j;
        if (rem >= c) rem -= c; else { mj = j; break; }
    }
    ml = mj + rem;
}

__device__ __forceinline__ float sym_entry(int deg, int mi, int mj, int ml,
                                           int o, int a,
                                           const float* __restrict__ U1,
                                           const float* __restrict__ U2,
                                           const float* __restrict__ U3) {
    float s = 0.f;
    if (deg == 3) {
        const size_t ob = (size_t)o * 9;
        float s6 =
            U3[(((ob + mi) * 9 + mj) * 9 + ml) * NA3 + a] +
            U3[(((ob + mi) * 9 + ml) * 9 + mj) * NA3 + a] +
            U3[(((ob + mj) * 9 + mi) * 9 + ml) * NA3 + a] +
            U3[(((ob + mj) * 9 + ml) * 9 + mi) * NA3 + a] +
            U3[(((ob + ml) * 9 + mi) * 9 + mj) * NA3 + a] +
            U3[(((ob + ml) * 9 + mj) * 9 + mi) * NA3 + a];
        float scale = (mi == ml) ? (1.f / 6.f)
                     : ((mi == mj || mj == ml) ? 0.5f : 1.f);
        s = s6 * scale;
    } else if (deg == 2 && a < NA2) {
        float s2 = U2[(((size_t)o * 9 + mi) * 9 + mj) * NA2 + a] +
                   U2[(((size_t)o * 9 + mj) * 9 + mi) * NA2 + a];
        s = (mi == mj) ? 0.5f * s2 : s2;
    } else if (deg == 1 && a < NA1) {
        s = U1[((size_t)o * 9 + mi) * NA1 + a];
    }
    return s;
}

__device__ __forceinline__ float proj_dot(const float* __restrict__ proj_row,
                                          const float* __restrict__ UsT,
                                          int deg, int aoff, int o) {
    float s = 0.f;
    if (deg == 3) {
#pragma unroll
        for (int b = 0; b < NA3; b++)
            s = fmaf(proj_row[aoff + b], UsT[b * 12 + o], s);
    } else if (deg == 2) {
#pragma unroll
        for (int b = 0; b < NA2; b++)
            s = fmaf(proj_row[aoff + b], UsT[b * 12 + o], s);
    } else if (deg == 1) {
#pragma unroll
        for (int b = 0; b < NA1; b++)
            s = fmaf(proj_row[aoff + b], UsT[b * 12 + o], s);
    }
    return s;
}

// ---------------------------------------------------------------------------
// Kernel B: one block per monomial PAIR (110 blocks), 640 threads = (e,k).
// Writes g_SP[ek][p][o*2+parity] — the exact layout eval consumes, so eval's
// staging is a raw vector copy (the round-13 transpose is gone).
//   Phase 1: UsT for even monomial (t<162) and odd (192<=t<354) in parallel.
//   Phase 2: Vp[a][o*2+par] = sum_b proj[a][aoff+b]*UsT[b][o]  (both parities)
//   Phase 3: 9 packed accumulators: acc_o = sum_a (Ve,Vo) * (w,w)
// ---------------------------------------------------------------------------
__global__ void __launch_bounds__(NEK)
coeff_kernel(const float* __restrict__ w,
             const float* __restrict__ proj,
             const float* __restrict__ U1,
             const float* __restrict__ U2,
             const float* __restrict__ U3) {
    const int p = blockIdx.x;
    const int t = threadIdx.x;

    // prefetch w (hides LDG latency under phases 1-2)
    const int e = t >> 6, k = t & 63;
    float wr[ATOT];
#pragma unroll
    for (int a = 0; a < ATOT; a++)
        wr[a] = w[((size_t)e * ATOT + a) * KCH + k];

    int mi_e, mj_e, ml_e, mi_o, mj_o, ml_o;
    decode_m(2 * p,     mi_e, mj_e, ml_e);
    decode_m(2 * p + 1, mi_o, mj_o, ml_o);
    const int deg_e  = (ml_e < 9) ? 3 : (mj_e < 9) ? 2 : (mi_e < 9) ? 1 : 0;
    const int deg_o  = (ml_o < 9) ? 3 : (mj_o < 9) ? 2 : (mi_o < 9) ? 1 : 0;
    const int aoff_e = (deg_e == 3) ? (NA1 + NA2) : (deg_e == 2) ? NA1 : 0;
    const int aoff_o = (deg_o == 3) ? (NA1 + NA2) : (deg_o == 2) ? NA1 : 0;

    __shared__ __align__(16) float UsT2[2][NA3 * 12];  // [parity][b][o]
    __shared__ __align__(16) float Vp[ATOT * VROW];    // [a][o*2+parity]

    if (t < 2 * NA3 * 12) ((float*)UsT2)[t] = 0.f;
    __syncthreads();

    if (t < 9 * NA3) {                       // even monomial
        int o = t / NA3, a = t % NA3;
        UsT2[0][a * 12 + o] = sym_entry(deg_e, mi_e, mj_e, ml_e, o, a, U1, U2, U3);
    } else if (t >= 192 && t < 192 + 9 * NA3) {  // odd monomial
        int t2 = t - 192;
        int o = t2 / NA3, a = t2 % NA3;
        UsT2[1][a * 12 + o] = sym_entry(deg_o, mi_o, mj_o, ml_o, o, a, U1, U2, U3);
    }
    __syncthreads();

    if (t < ATOT * 12) {
        int a = t / 12, o = t % 12;
        if (o < 9) {
            const float* prow = proj + a * ATOT;
            Vp[a * VROW + o * 2 + 0] = proj_dot(prow, UsT2[0], deg_e, aoff_e, o);
            Vp[a * VROW + o * 2 + 1] = proj_dot(prow, UsT2[1], deg_o, aoff_o, o);
        }
    }
    __syncthreads();

    // Phase 3: packed (even,odd) accumulation per output o
    unsigned long long ac0 = 0, ac1 = 0, ac2 = 0, ac3 = 0, ac4 = 0,
                       ac5 = 0, ac6 = 0, ac7 = 0, ac8 = 0;
#pragma unroll
    for (int a = 0; a < ATOT; a++) {
        const float* row = Vp + a * VROW;
        ulonglong2 cA = *(const ulonglong2*)row;         // o0,o1 pairs
        ulonglong2 cB = *(const ulonglong2*)(row + 4);   // o2,o3
        ulonglong2 cC = *(const ulonglong2*)(row + 8);   // o4,o5
        ulonglong2 cD = *(const ulonglong2*)(row + 12);  // o6,o7
        unsigned long long c8 = *(const unsigned long long*)(row + 16);
        unsigned long long wv = dup_f32(wr[a]);
        ffma2(ac0, cA.x, wv);
        ffma2(ac1, cA.y, wv);
        ffma2(ac2, cB.x, wv);
        ffma2(ac3, cB.y, wv);
        ffma2(ac4, cC.x, wv);
        ffma2(ac5, cC.y, wv);
        ffma2(ac6, cD.x, wv);
        ffma2(ac7, cD.y, wv);
        ffma2(ac8, c8,   wv);
    }

    float* dst = g_SP + (size_t)t * PBLK + p * PROW;   // 16B-aligned
    ulonglong2* d2 = (ulonglong2*)dst;
    d2[0] = make_ulonglong2(ac0, ac1);
    d2[1] = make_ulonglong2(ac2, ac3);
    d2[2] = make_ulonglong2(ac4, ac5);
    d2[3] = make_ulonglong2(ac6, ac7);
    ((unsigned long long*)dst)[8] = ac8;
}

// ---------------------------------------------------------------------------
// Eval inner body (pairs): accumulate monomials in [MS, ME), MS/ME even.
// ---------------------------------------------------------------------------
template <int MS, int ME>
__device__ __forceinline__ void eval_pairs(const float* __restrict__ Cs,
                                           const float v[10], float r[9]) {
    unsigned long long ac0 = 0, ac1 = 0, ac2 = 0, ac3 = 0, ac4 = 0,
                       ac5 = 0, ac6 = 0, ac7 = 0, ac8 = 0;
    float tm0 = 0.f;
    int m = 0;
#pragma unroll
    for (int i = 0; i < 10; i++) {
#pragma unroll
        for (int j = i; j < 10; j++) {
            float pij = v[i] * v[j];
#pragma unroll
            for (int l = j; l < 10; l++) {
                if (m >= MS && m < ME) {
                    float tm = pij * v[l];
                    if ((m & 1) == 0) {
                        tm0 = tm;
                    } else {
                        unsigned long long tp = pack_f32x2(tm0, tm);
                        const float* row = Cs + (m >> 1) * PROW;
                        ulonglong2 cA = *(const ulonglong2*)row;
                        ulonglong2 cB = *(const ulonglong2*)(row + 4);
                        ulonglong2 cC = *(const ulonglong2*)(row + 8);
                        ulonglong2 cD = *(const ulonglong2*)(row + 12);
                        unsigned long long c8 = *(const unsigned long long*)(row + 16);
                        ffma2(ac0, cA.x, tp);
                        ffma2(ac1, cA.y, tp);
                        ffma2(ac2, cB.x, tp);
                        ffma2(ac3, cB.y, tp);
                        ffma2(ac4, cC.x, tp);
                        ffma2(ac5, cC.y, tp);
                        ffma2(ac6, cD.x, tp);
                        ffma2(ac7, cD.y, tp);
                        ffma2(ac8, c8,   tp);
                    }
                }
                m++;
            }
        }
    }
    float lo, hi;
    unpack2(ac0, lo, hi); r[0] = lo + hi;
    unpack2(ac1, lo, hi); r[1] = lo + hi;
    unpack2(ac2, lo, hi); r[2] = lo + hi;
    unpack2(ac3, lo, hi); r[3] = lo + hi;
    unpack2(ac4, lo, hi); r[4] = lo + hi;
    unpack2(ac5, lo, hi); r[5] = lo + hi;
    unpack2(ac6, lo, hi); r[6] = lo + hi;
    unpack2(ac7, lo, hi); r[7] = lo + hi;
    unpack2(ac8, lo, hi); r[8] = lo + hi;
}

// ---------------------------------------------------------------------------
// Kernel C: evaluate. One block per (k, e), 384 threads:
//   atom = tid & 127, third = tid >> 7 sums monomials [0,74)/[74,148)/[148,220).
//   Cs staging is a raw float4 copy (layout already pair-interleaved).
// ---------------------------------------------------------------------------
__global__ void __launch_bounds__(384, 3)
eval_kernel(const float* __restrict__ x,
            const int* __restrict__ counts,
            float* __restrict__ out) {
    const int k = blockIdx.x;
    const int e = blockIdx.y;
    const int ek = e * KCH + k;

    __shared__ __align__(16) float Cs[PBLK];          // 8.8 KB
    __shared__ float Red[2 * 128 * RROW];
    __shared__ float Xs[128 * RROW];

    {
        const float4* src = (const float4*)(g_SP + (size_t)ek * PBLK);
        float4* dst = (float4*)Cs;
        for (int tidx = threadIdx.x; tidx < PBLK / 4; tidx += blockDim.x)
            dst[tidx] = src[tidx];
    }

    int start = 0, cnt = 0;
#pragma unroll
    for (int t = 0; t < NSPEC; t++) {
        int c = counts[t];
        if (t < e) start += c;
        if (t == e) cnt = c;
    }

    // Coalesced cooperative x stage: Xs[atom][d] = x[(n*64+k)*9+d]
    for (int idx = threadIdx.x; idx < 128 * D; idx += blockDim.x) {
        int atom = idx / D, d = idx - atom * D;
        int a = (atom < cnt) ? atom : (cnt - 1);     // clamp (avoid OOB)
        int n = start + a;
        Xs[atom * RROW + d] = x[((size_t)n * KCH + k) * D + d];
    }
    __syncthreads();

    const int tid  = threadIdx.x;
    const int atom = tid & 127;
    const int q    = tid >> 7;          // third: 0,1,2

    float v[10];
#pragma unroll
    for (int t = 0; t < 9; t++) v[t] = Xs[atom * RROW + t];
    v[9] = 1.f;

    float r[9];
    if (q == 0)      eval_pairs<0,  T1>(Cs, v, r);
    else if (q == 1) eval_pairs<T1, T2>(Cs, v, r);
    else             eval_pairs<T2, NM>(Cs, v, r);

    if (q != 0) {
        float* rr = Red + ((q - 1) * 128 + atom) * RROW;
#pragma unroll
        for (int o = 0; o < 9; o++) rr[o] = r[o];
    }
    __syncthreads();

    if (q == 0) {
        const float* r1 = Red + (0 * 128 + atom) * RROW;
        const float* r2 = Red + (1 * 128 + atom) * RROW;
        float* rr = Xs + atom * RROW;
#pragma unroll
        for (int o = 0; o < 9; o++)
            rr[o] = r[o] + r1[o] + r2[o];
    }
    __syncthreads();

    for (int idx = threadIdx.x; idx < cnt * D; idx += blockDim.x) {
        int atom2 = idx / D, d = idx - atom2 * D;
        int n = start + atom2;
        out[((size_t)n * KCH + k) * D + d] = Xs[atom2 * RROW + d];
    }
}

// ---------------------------------------------------------------------------
extern "C" void kernel_launch(void* const* d_in, const int* in_sizes, int n_in,
                              void* d_out, int out_size) {
    const float* x      = (const float*)d_in[0];
    const int*   counts = (const int*)  d_in[1];
    const float* w      = (const float*)d_in[2];
    const float* proj   = (const float*)d_in[3];
    const float* U1     = (const float*)d_in[4];
    const float* U2     = (const float*)d_in[5];
    const float* U3     = (const float*)d_in[6];
    float* out = (float*)d_out;

    coeff_kernel<<<NPAIR, NEK>>>(w, proj, U1, U2, U3);
    dim3 grid(KCH, NSPEC);
    eval_kernel<<<grid, 384>>>(x, counts, out);
}

// round 16
// speedup vs baseline: 1.2152x; 1.0760x over previous
#include <cuda_runtime.h>
#include <cstddef>

#define NSPEC 10
#define KCH   64
#define D     9
#define NA1   3
#define NA2   8
#define NA3   18
#define ATOT  29
#define NEK   (NSPEC * KCH)   // 640 (species, channel) combos
#define NM    220             // C(12,3): monomials i<=j<=l over 10 vars (v9 == 1)
#define NPAIR (NM / 2)        // 110 monomial pairs
#define PROW  20              // floats per pair row: [o0e,o0o,...,o8e,o8o,pad,pad]
#define PBLK  (NPAIR * PROW)  // 2200 floats per (e,k)
#define VROW  20              // V pair row stride in coeff smem
#define RROW  13              // x/out row stride (odd -> conflict-free banks)

// Scratch (device global — allocation-free per harness rules)
__device__ float g_SP[(size_t)NEK * PBLK];   // pair-interleaved coeffs, 5.6 MB

// ---------------------------------------------------------------------------
// packed f32x2 helpers (sm_103a FFMA2 — PTX only)
// ---------------------------------------------------------------------------
__device__ __forceinline__ void ffma2(unsigned long long& d,
                                      unsigned long long a,
                                      unsigned long long b) {
    asm("fma.rn.f32x2 %0, %1, %2, %0;" : "+l"(d) : "l"(a), "l"(b));
}
__device__ __forceinline__ unsigned long long dup_f32(float t) {
    unsigned long long r;
    asm("mov.b64 %0, {%1, %1};" : "=l"(r) : "r"(__float_as_uint(t)));
    return r;
}
__device__ __forceinline__ unsigned long long pack_f32x2(float lo, float hi) {
    unsigned long long r;
    asm("mov.b64 %0, {%1, %2};" : "=l"(r)
        : "r"(__float_as_uint(lo)), "r"(__float_as_uint(hi)));
    return r;
}
__device__ __forceinline__ void unpack2(unsigned long long p, float& lo, float& hi) {
    unsigned a, b;
    asm("mov.b64 {%0, %1}, %2;" : "=r"(a), "=r"(b) : "l"(p));
    lo = __uint_as_float(a); hi = __uint_as_float(b);
}

// ---------------------------------------------------------------------------
// Monomial decode + symmetrized-U helpers (coeff kernel)
// ---------------------------------------------------------------------------
__device__ __forceinline__ void decode_m(int m, int& mi, int& mj, int& ml) {
    int rem = m; mi = 0;
#pragma unroll
    for (int i = 0; i < 10; i++) {
        int tt = 10 - i, c = tt * (tt + 1) / 2;
        if (rem >= c) rem -= c; else { mi = i; break; }
    }
    mj = mi;
#pragma unroll
    for (int j = 0; j < 10; j++) {
        if (j < mi) continue;
        int c = 10 - j;
        if (rem >= c) rem -= c; else { mj = j; break; }
    }
    ml = mj + rem;
}

__device__ __forceinline__ float sym_entry(int deg, int mi, int mj, int ml,
                                           int o, int a,
                                           const float* __restrict__ U1,
                                           const float* __restrict__ U2,
                                           const float* __restrict__ U3) {
    float s = 0.f;
    if (deg == 3) {
        const size_t ob = (size_t)o * 9;
        float s6 =
            U3[(((ob + mi) * 9 + mj) * 9 + ml) * NA3 + a] +
            U3[(((ob + mi) * 9 + ml) * 9 + mj) * NA3 + a] +
            U3[(((ob + mj) * 9 + mi) * 9 + ml) * NA3 + a] +
            U3[(((ob + mj) * 9 + ml) * 9 + mi) * NA3 + a] +
            U3[(((ob + ml) * 9 + mi) * 9 + mj) * NA3 + a] +
            U3[(((ob + ml) * 9 + mj) * 9 + mi) * NA3 + a];
        float scale = (mi == ml) ? (1.f / 6.f)
                     : ((mi == mj || mj == ml) ? 0.5f : 1.f);
        s = s6 * scale;
    } else if (deg == 2 && a < NA2) {
        float s2 = U2[(((size_t)o * 9 + mi) * 9 + mj) * NA2 + a] +
                   U2[(((size_t)o * 9 + mj) * 9 + mi) * NA2 + a];
        s = (mi == mj) ? 0.5f * s2 : s2;
    } else if (deg == 1 && a < NA1) {
        s = U1[((size_t)o * 9 + mi) * NA1 + a];
    }
    return s;
}

__device__ __forceinline__ float proj_dot(const float* __restrict__ proj_row,
                                          const float* __restrict__ UsT,
                                          int deg, int aoff, int o) {
    float s = 0.f;
    if (deg == 3) {
#pragma unroll
        for (int b = 0; b < NA3; b++)
            s = fmaf(proj_row[aoff + b], UsT[b * 12 + o], s);
    } else if (deg == 2) {
#pragma unroll
        for (int b = 0; b < NA2; b++)
            s = fmaf(proj_row[aoff + b], UsT[b * 12 + o], s);
    } else if (deg == 1) {
#pragma unroll
        for (int b = 0; b < NA1; b++)
            s = fmaf(proj_row[aoff + b], UsT[b * 12 + o], s);
    }
    return s;
}

// ---------------------------------------------------------------------------
// Kernel B: one block per monomial PAIR (110 blocks), 640 threads = (e,k).
// UNCHANGED from the passing round-15 kernel. Writes g_SP in the pair layout
// eval consumes directly.
// ---------------------------------------------------------------------------
__global__ void __launch_bounds__(NEK)
coeff_kernel(const float* __restrict__ w,
             const float* __restrict__ proj,
             const float* __restrict__ U1,
             const float* __restrict__ U2,
             const float* __restrict__ U3) {
    const int p = blockIdx.x;
    const int t = threadIdx.x;

    const int e = t >> 6, k = t & 63;
    float wr[ATOT];
#pragma unroll
    for (int a = 0; a < ATOT; a++)
        wr[a] = w[((size_t)e * ATOT + a) * KCH + k];

    int mi_e, mj_e, ml_e, mi_o, mj_o, ml_o;
    decode_m(2 * p,     mi_e, mj_e, ml_e);
    decode_m(2 * p + 1, mi_o, mj_o, ml_o);
    const int deg_e  = (ml_e < 9) ? 3 : (mj_e < 9) ? 2 : (mi_e < 9) ? 1 : 0;
    const int deg_o  = (ml_o < 9) ? 3 : (mj_o < 9) ? 2 : (mi_o < 9) ? 1 : 0;
    const int aoff_e = (deg_e == 3) ? (NA1 + NA2) : (deg_e == 2) ? NA1 : 0;
    const int aoff_o = (deg_o == 3) ? (NA1 + NA2) : (deg_o == 2) ? NA1 : 0;

    __shared__ __align__(16) float UsT2[2][NA3 * 12];  // [parity][b][o]
    __shared__ __align__(16) float Vp[ATOT * VROW];    // [a][o*2+parity]

    if (t < 2 * NA3 * 12) ((float*)UsT2)[t] = 0.f;
    __syncthreads();

    if (t < 9 * NA3) {
        int o = t / NA3, a = t % NA3;
        UsT2[0][a * 12 + o] = sym_entry(deg_e, mi_e, mj_e, ml_e, o, a, U1, U2, U3);
    } else if (t >= 192 && t < 192 + 9 * NA3) {
        int t2 = t - 192;
        int o = t2 / NA3, a = t2 % NA3;
        UsT2[1][a * 12 + o] = sym_entry(deg_o, mi_o, mj_o, ml_o, o, a, U1, U2, U3);
    }
    __syncthreads();

    if (t < ATOT * 12) {
        int a = t / 12, o = t % 12;
        if (o < 9) {
            const float* prow = proj + a * ATOT;
            Vp[a * VROW + o * 2 + 0] = proj_dot(prow, UsT2[0], deg_e, aoff_e, o);
            Vp[a * VROW + o * 2 + 1] = proj_dot(prow, UsT2[1], deg_o, aoff_o, o);
        }
    }
    __syncthreads();

    unsigned long long ac0 = 0, ac1 = 0, ac2 = 0, ac3 = 0, ac4 = 0,
                       ac5 = 0, ac6 = 0, ac7 = 0, ac8 = 0;
#pragma unroll
    for (int a = 0; a < ATOT; a++) {
        const float* row = Vp + a * VROW;
        ulonglong2 cA = *(const ulonglong2*)row;
        ulonglong2 cB = *(const ulonglong2*)(row + 4);
        ulonglong2 cC = *(const ulonglong2*)(row + 8);
        ulonglong2 cD = *(const ulonglong2*)(row + 12);
        unsigned long long c8 = *(const unsigned long long*)(row + 16);
        unsigned long long wv = dup_f32(wr[a]);
        ffma2(ac0, cA.x, wv);
        ffma2(ac1, cA.y, wv);
        ffma2(ac2, cB.x, wv);
        ffma2(ac3, cB.y, wv);
        ffma2(ac4, cC.x, wv);
        ffma2(ac5, cC.y, wv);
        ffma2(ac6, cD.x, wv);
        ffma2(ac7, cD.y, wv);
        ffma2(ac8, c8,   wv);
    }

    float* dst = g_SP + (size_t)t * PBLK + p * PROW;
    ulonglong2* d2 = (ulonglong2*)dst;
    d2[0] = make_ulonglong2(ac0, ac1);
    d2[1] = make_ulonglong2(ac2, ac3);
    d2[2] = make_ulonglong2(ac4, ac5);
    d2[3] = make_ulonglong2(ac6, ac7);
    ((unsigned long long*)dst)[8] = ac8;
}

// ---------------------------------------------------------------------------
// Eval inner body (OUTPUT-split): group G computes outputs {3G, 3G+1, 3G+2}
// over ALL 220 monomials. Only 3 packed accumulators (6 regs). Per pair:
// 1 LDS.128 + 1 LDS.64 at compile-time offset 6G within the 80-byte pair row.
// ---------------------------------------------------------------------------
template <int G>
__device__ __forceinline__ void eval_out3(const float* __restrict__ Cs,
                                          const float v[10], float r[3]) {
    unsigned long long a0 = 0, a1 = 0, a2 = 0;
    float tm0 = 0.f;
    int m = 0;
#pragma unroll
    for (int i = 0; i < 10; i++) {
#pragma unroll
        for (int j = i; j < 10; j++) {
            float pij = v[i] * v[j];
#pragma unroll
            for (int l = j; l < 10; l++) {
                float tm = pij * v[l];
                if ((m & 1) == 0) {
                    tm0 = tm;
                } else {
                    unsigned long long tp = pack_f32x2(tm0, tm);
                    const float* row = Cs + (m >> 1) * PROW;
                    unsigned long long c0, c1, c2;
                    if (G == 0) {            // floats [0,6): 16B-aligned first
                        ulonglong2 cA = *(const ulonglong2*)(row);
                        c0 = cA.x; c1 = cA.y;
                        c2 = *(const unsigned long long*)(row + 4);
                    } else if (G == 1) {     // floats [6,12): u64 then 16B-aligned
                        c0 = *(const unsigned long long*)(row + 6);
                        ulonglong2 cB = *(const ulonglong2*)(row + 8);
                        c1 = cB.x; c2 = cB.y;
                    } else {                 // floats [12,18): 16B-aligned first
                        ulonglong2 cC = *(const ulonglong2*)(row + 12);
                        c0 = cC.x; c1 = cC.y;
                        c2 = *(const unsigned long long*)(row + 16);
                    }
                    ffma2(a0, c0, tp);
                    ffma2(a1, c1, tp);
                    ffma2(a2, c2, tp);
                }
                m++;
            }
        }
    }
    float lo, hi;
    unpack2(a0, lo, hi); r[0] = lo + hi;
    unpack2(a1, lo, hi); r[1] = lo + hi;
    unpack2(a2, lo, hi); r[2] = lo + hi;
}

// ---------------------------------------------------------------------------
// Kernel C: evaluate. One block per (k, e), 384 threads:
//   atom = tid & 127; group g = tid >> 7 owns outputs {3g,3g+1,3g+2}.
//   Disjoint outputs -> NO cross-group reduction. Results staged in Os for
//   the coalesced store sweep. x staged coalesced in Xs as before.
// ---------------------------------------------------------------------------
__global__ void __launch_bounds__(384, 4)
eval_kernel(const float* __restrict__ x,
            const int* __restrict__ counts,
            float* __restrict__ out) {
    const int k = blockIdx.x;
    const int e = blockIdx.y;
    const int ek = e * KCH + k;

    __shared__ __align__(16) float Cs[PBLK];          // 8.8 KB
    __shared__ float Xs[128 * RROW];                  // staged x
    __shared__ float Os[128 * RROW];                  // staged outputs

    {
        const float4* src = (const float4*)(g_SP + (size_t)ek * PBLK);
        float4* dst = (float4*)Cs;
        for (int tidx = threadIdx.x; tidx < PBLK / 4; tidx += blockDim.x)
            dst[tidx] = src[tidx];
    }

    int start = 0, cnt = 0;
#pragma unroll
    for (int t = 0; t < NSPEC; t++) {
        int c = counts[t];
        if (t < e) start += c;
        if (t == e) cnt = c;
    }

    // Coalesced cooperative x stage: Xs[atom][d] = x[(n*64+k)*9+d]
    for (int idx = threadIdx.x; idx < 128 * D; idx += blockDim.x) {
        int atom = idx / D, d = idx - atom * D;
        int a = (atom < cnt) ? atom : (cnt - 1);     // clamp (avoid OOB)
        int n = start + a;
        Xs[atom * RROW + d] = x[((size_t)n * KCH + k) * D + d];
    }
    __syncthreads();

    const int tid  = threadIdx.x;
    const int atom = tid & 127;
    const int g    = tid >> 7;          // output group: 0,1,2

    float v[10];
#pragma unroll
    for (int t = 0; t < 9; t++) v[t] = Xs[atom * RROW + t];
    v[9] = 1.f;

    float r[3];
    if (g == 0)      eval_out3<0>(Cs, v, r);
    else if (g == 1) eval_out3<1>(Cs, v, r);
    else             eval_out3<2>(Cs, v, r);

    {
        float* rr = Os + atom * RROW + 3 * g;
        rr[0] = r[0]; rr[1] = r[1]; rr[2] = r[2];
    }
    __syncthreads();

    for (int idx = threadIdx.x; idx < cnt * D; idx += blockDim.x) {
        int atom2 = idx / D, d = idx - atom2 * D;
        int n = start + atom2;
        out[((size_t)n * KCH + k) * D + d] = Os[atom2 * RROW + d];
    }
}

// ---------------------------------------------------------------------------
extern "C" void kernel_launch(void* const* d_in, const int* in_sizes, int n_in,
                              void* d_out, int out_size) {
    const float* x      = (const float*)d_in[0];
    const int*   counts = (const int*)  d_in[1];
    const float* w      = (const float*)d_in[2];
    const float* proj   = (const float*)d_in[3];
    const float* U1     = (const float*)d_in[4];
    const float* U2     = (const float*)d_in[5];
    const float* U3     = (const float*)d_in[6];
    float* out = (float*)d_out;

    coeff_kernel<<<NPAIR, NEK>>>(w, proj, U1, U2, U3);
    dim3 grid(KCH, NSPEC);
    eval_kernel<<<grid, 384>>>(x, counts, out);
}